// round 6
// baseline (speedup 1.0000x reference)
#include <cuda_runtime.h>
#include <cuda_bf16.h>
#include <cstdint>

// ---------------------------------------------------------------------------
// TargetTokenEncoder: hist/stats -> MLP(14->256, exact GELU) -> GEMM(256x256)
// Stage C via warp-level HMMA (mma.sync m16n8k16 bf16, fp32 accum),
// bf16x3 split precision: Ah*Bh + Ah*Bl + Al*Bh (rel err ~5e-6).
// R6: two 32-row halves software-pipelined: GEMM(h0) overlaps MLP(h1),
//     GEMM(h1) overlaps epilogue(h0). B double-buffered via cp.async that
//     copies only data granules; stats live in B1 row-pad bytes.
// ---------------------------------------------------------------------------

static constexpr int S      = 128;
static constexpr int TD     = 256;
static constexpr int TILE_M = 64;

static constexpr int A_STRIDE = 512;              // XOR-swizzled, no pad
static constexpr int N_KC    = 16;                // k-chunks of 16 cols
static constexpr int B_STRIDE = 48;               // 32B data + 16B pad
static constexpr int B_HALF  = 256 * B_STRIDE;    // 12288 per plane

static constexpr int OFF_A_HI  = 0;               // 64 x 512 = 32768
static constexpr int OFF_A_LO  = 32768;
static constexpr int OFF_B0    = 65536;           // buffer 0 (hi, then lo)
static constexpr int OFF_B1    = 90112;           // buffer 1 (hi, then lo)
static constexpr int SMEM_BYTES = 114688;         // 2 CTAs/SM

static constexpr int D_A_LO = 32768;
static constexpr int D_B_LO = B_HALF;             // 12288 within a buffer

// stats[r][j] lives in B1 pad bytes: row 4r+j4, bytes 32..47 (never cp.async'd)
#define STAT_ADDR(base, r) ((base) + OFF_B1 + (uint32_t)(4 * (r)) * 48 + 32)

// persistent scratch: w2 split-bf16, exact smem B-chunk byte image per kc
__device__ __align__(16) __nv_bfloat16 g_b_hi[N_KC * 256 * (B_STRIDE / 2)];
__device__ __align__(16) __nv_bfloat16 g_b_lo[N_KC * 256 * (B_STRIDE / 2)];

__device__ __forceinline__ uint32_t smem_u32(const void* p) {
    uint32_t a;
    asm("{ .reg .u64 t; cvta.to.shared.u64 t, %1; cvt.u32.u64 %0, t; }" : "=r"(a) : "l"(p));
    return a;
}

__device__ __forceinline__ void cp16(uint32_t saddr, const void* gptr) {
    asm volatile("cp.async.cg.shared.global [%0], [%1], 16;"
                 :: "r"(saddr), "l"(gptr) : "memory");
}
__device__ __forceinline__ void cp_commit() {
    asm volatile("cp.async.commit_group;" ::: "memory");
}
__device__ __forceinline__ void cp_wait0() {
    asm volatile("cp.async.wait_group 0;" ::: "memory");
}
__device__ __forceinline__ void cp_wait1() {
    asm volatile("cp.async.wait_group 1;" ::: "memory");
}

__device__ __forceinline__ void ldm4(uint32_t* r, uint32_t addr) {
    asm volatile("ldmatrix.sync.aligned.m8n8.x4.shared.b16 {%0,%1,%2,%3}, [%4];"
                 : "=r"(r[0]), "=r"(r[1]), "=r"(r[2]), "=r"(r[3]) : "r"(addr));
}

__device__ __forceinline__ void mma_bf16(float* c, const uint32_t* a,
                                         uint32_t b0, uint32_t b1) {
    asm volatile("mma.sync.aligned.m16n8k16.row.col.f32.bf16.bf16.f32 "
                 "{%0,%1,%2,%3}, {%4,%5,%6,%7}, {%8,%9}, {%0,%1,%2,%3};"
                 : "+f"(c[0]), "+f"(c[1]), "+f"(c[2]), "+f"(c[3])
                 : "r"(a[0]), "r"(a[1]), "r"(a[2]), "r"(a[3]), "r"(b0), "r"(b1));
}

// ---------------- prep kernel: split w2 into chunked smem-image layout
__global__ __launch_bounds__(256)
void prep_kernel(const float* __restrict__ w2) {
    int idx = blockIdx.x * 256 + threadIdx.x;
    const int total = N_KC * 256 * (B_STRIDE / 2);      // 98304
    if (idx >= total) return;
    int kc  = idx / (256 * 24);
    int rem = idx % (256 * 24);
    int nl  = rem / 24;
    int j   = rem % 24;
    float v = (j < 16) ? __ldg(w2 + (size_t)(kc * 16 + j) * TD + nl) : 0.0f;
    __nv_bfloat16 hi = __float2bfloat16(v);
    float lo = v - __bfloat162float(hi);
    g_b_hi[idx] = hi;
    g_b_lo[idx] = __float2bfloat16(lo);
}

// copy one chunk's DATA granules only (pads untouched -> stats safe)
__device__ __forceinline__ void fill_b_copy(uint32_t sbuf, int kc,
                                            int tid0, int nthreads) {
    const char* shi = reinterpret_cast<const char*>(g_b_hi) + kc * B_HALF;
    const char* slo = reinterpret_cast<const char*>(g_b_lo) + kc * B_HALF;
    for (int i = tid0; i < 512; i += nthreads) {       // 256 rows x 2 granules
        uint32_t off = (uint32_t)((i >> 1) * 48 + (i & 1) * 16);
        cp16(sbuf + off, shi + off);
        cp16(sbuf + D_B_LO + off, slo + off);
    }
    cp_commit();
}

__global__ __launch_bounds__(256, 2)
void tte_kernel(const int* __restrict__ y, const float* __restrict__ w1,
                const float* __restrict__ b1,
                const float* __restrict__ b2, float* __restrict__ out)
{
    extern __shared__ char smem[];
    const uint32_t sb = smem_u32(smem);
    const int tid = threadIdx.x;
    const int wid = tid >> 5;
    const int lid = tid & 31;

    // ---------------- Phase 1: threads 0-63 hist+stats (written to B1 pads);
    //                  threads 64-255 prefetch B chunk 0 into buffer 0
    if (tid < TILE_M) {
        const int4* p = reinterpret_cast<const int4*>(
            y + ((size_t)blockIdx.x * TILE_M + tid) * S);
        uint32_t a0 = 0, a1 = 0, a2 = 0;   // 4x8-bit packed counters
        #pragma unroll
        for (int i = 0; i < S / 4; i++) {
            int4 v = __ldg(p + i);
            { int x = v.x; uint32_t b = 1u << ((x & 3) << 3);
              if (x < 4) a0 += b; else if (x < 8) a1 += b; else a2 += b; }
            { int x = v.y; uint32_t b = 1u << ((x & 3) << 3);
              if (x < 4) a0 += b; else if (x < 8) a1 += b; else a2 += b; }
            { int x = v.z; uint32_t b = 1u << ((x & 3) << 3);
              if (x < 4) a0 += b; else if (x < 8) a1 += b; else a2 += b; }
            { int x = v.w; uint32_t b = 1u << ((x & 3) << 3);
              if (x < 4) a0 += b; else if (x < 8) a1 += b; else a2 += b; }
        }
        int cnt[10];
        float pr[10];
        #pragma unroll
        for (int c = 0; c < 10; c++) {
            uint32_t a = (c < 4) ? a0 : ((c < 8) ? a1 : a2);
            cnt[c] = (int)((a >> ((c & 3) * 8)) & 0xFF);
            pr[c]  = (float)cnt[c] * (1.0f / 128.0f);   // exact in fp32
        }
        float ent = 0.0f, pm = 0.0f, nnz = 0.0f;
        #pragma unroll
        for (int c = 0; c < 10; c++) {
            ent -= pr[c] * logf(pr[c] + 1e-6f);         // p==0 -> exactly 0
            pm   = fmaxf(pm, pr[c]);
            nnz += (cnt[c] > 0) ? 1.0f : 0.0f;
        }
        char* pb = smem + OFF_B1 + (uint32_t)(4 * tid) * 48 + 32;
        *reinterpret_cast<float4*>(pb)       = make_float4(pr[0], pr[1], pr[2], pr[3]);
        *reinterpret_cast<float4*>(pb + 48)  = make_float4(pr[4], pr[5], pr[6], pr[7]);
        *reinterpret_cast<float4*>(pb + 96)  = make_float4(pr[8], pr[9], nnz, ent);
        *reinterpret_cast<float4*>(pb + 144) = make_float4(128.0f, pm, 0.0f, 0.0f);
    } else {
        fill_b_copy(sb + OFF_B0, 0, tid - 64, 192);
    }
    __syncthreads();

    // MLP state: thread t owns h column n=t
    float wv[14];
    #pragma unroll
    for (int k = 0; k < 14; k++) wv[k] = __ldg(w1 + k * TD + tid);
    const float bb1 = __ldg(b1 + tid);
    const uint32_t gcol = (uint32_t)(tid >> 3);        // 16B granule of col
    const uint32_t gbyt = (uint32_t)((tid & 7) << 1);  // byte within granule

    // gelu(stats[r] @ w1 + b1) -> split bf16 into A planes, row r
    auto mlp_row = [&](int r) {
        const char* pb = smem + OFF_B1 + (uint32_t)(4 * r) * 48 + 32;
        float4 s0 = *reinterpret_cast<const float4*>(pb);
        float4 s1 = *reinterpret_cast<const float4*>(pb + 48);
        float4 s2 = *reinterpret_cast<const float4*>(pb + 96);
        float4 s3 = *reinterpret_cast<const float4*>(pb + 144);
        float x = bb1;
        x = fmaf(s0.x, wv[0], x);  x = fmaf(s0.y, wv[1], x);
        x = fmaf(s0.z, wv[2], x);  x = fmaf(s0.w, wv[3], x);
        x = fmaf(s1.x, wv[4], x);  x = fmaf(s1.y, wv[5], x);
        x = fmaf(s1.z, wv[6], x);  x = fmaf(s1.w, wv[7], x);
        x = fmaf(s2.x, wv[8], x);  x = fmaf(s2.y, wv[9], x);
        x = fmaf(s2.z, wv[10], x); x = fmaf(s2.w, wv[11], x);
        x = fmaf(s3.x, wv[12], x); x = fmaf(s3.y, wv[13], x);
        float g = 0.5f * x * (1.0f + erff(x * 0.707106781186547524f));
        __nv_bfloat16 hi = __float2bfloat16(g);
        float rem = g - __bfloat162float(hi);
        __nv_bfloat16 lo = __float2bfloat16(rem);
        uint32_t off = (uint32_t)(r * A_STRIDE)
                     + (((gcol ^ (uint32_t)(r & 7)) << 4) | gbyt);
        *reinterpret_cast<__nv_bfloat16*>(smem + OFF_A_HI + off) = hi;
        *reinterpret_cast<__nv_bfloat16*>(smem + OFF_A_LO + off) = lo;
    };

    // ---------------- Phase 2: MLP half 0 (rows 0..31)  [chunk 0 in flight]
    for (int r = 0; r < 32; r++) mlp_row(r);
    __syncthreads();

    // ---------------- GEMM setup: 8 warps = 8 N-groups of 32 cols; M=32/half
    const int wn = wid;                // 0..7 -> N offset 32*wn
    const int j8 = lid >> 3;
    const int lr = lid & 7;

    uint32_t arow[2][2], arx[2][2];    // [half][mtile]
    #pragma unroll
    for (int h = 0; h < 2; h++)
        #pragma unroll
        for (int i = 0; i < 2; i++) {
            const int rr = h * 32 + i * 16 + ((j8 & 1) << 3) + lr;
            arow[h][i] = sb + OFF_A_HI + (uint32_t)(rr * A_STRIDE);
            arx[h][i]  = (uint32_t)(rr & 7);
        }
    const uint32_t agj = (uint32_t)(j8 >> 1);

    uint32_t brel[2];
    #pragma unroll
    for (int p = 0; p < 2; p++)
        brel[p] = (uint32_t)((wn * 32 + p * 16 + ((j8 >> 1) << 3) + lr) * B_STRIDE)
                + (uint32_t)((j8 & 1) << 4);

    float acc0[2][4][4], acc1[2][4][4];
    #pragma unroll
    for (int i = 0; i < 2; i++)
        #pragma unroll
        for (int j = 0; j < 4; j++)
            #pragma unroll
            for (int q = 0; q < 4; q++) { acc0[i][j][q] = 0.0f; acc1[i][j][q] = 0.0f; }

    // one chunk of HMMA for one half into acc
    auto gemm_chunk = [&](uint32_t bbuf, int kc, int h, float (&acc)[2][4][4]) {
        uint32_t aH[2][4], aL[2][4];
        #pragma unroll
        for (int i = 0; i < 2; i++) {
            const uint32_t ga = ((uint32_t)(kc * 2) + agj) ^ arx[h][i];
            ldm4(aH[i], arow[h][i] + (ga << 4));
            ldm4(aL[i], arow[h][i] + (ga << 4) + D_A_LO);
        }
        #pragma unroll
        for (int p = 0; p < 2; p++) {
            uint32_t bH[4], bL[4];
            ldm4(bH, bbuf + brel[p]);
            ldm4(bL, bbuf + brel[p] + D_B_LO);
            #pragma unroll
            for (int i = 0; i < 2; i++) {
                #pragma unroll
                for (int jj = 0; jj < 2; jj++) {
                    const int j = p * 2 + jj, hh = jj * 2;
                    mma_bf16(acc[i][j], aH[i], bH[hh], bH[hh + 1]); // Ah*Bh
                    mma_bf16(acc[i][j], aH[i], bL[hh], bL[hh + 1]); // Ah*Bl
                    mma_bf16(acc[i][j], aL[i], bH[hh], bH[hh + 1]); // Al*Bh
                }
            }
        }
    };

    const int g  = lid >> 2;
    const int tg = lid & 3;
    const size_t rbase = (size_t)blockIdx.x * TILE_M;
    auto store_frag = [&](const float* a4, int h, int i, int j) {
        const int col = wn * 32 + j * 8 + tg * 2;
        const float2 bbv = __ldg(reinterpret_cast<const float2*>(b2 + col));
        const size_t r0 = rbase + h * 32 + i * 16 + g;
        *reinterpret_cast<float2*>(out + r0 * TD + col) =
            make_float2(a4[0] + bbv.x, a4[1] + bbv.y);
        *reinterpret_cast<float2*>(out + (r0 + 8) * TD + col) =
            make_float2(a4[2] + bbv.x, a4[3] + bbv.y);
    };

    // ---------------- Loop 1: GEMM(h0) + interleaved MLP(h1)
    #pragma unroll 1
    for (int kc = 0; kc < N_KC; kc++) {
        fill_b_copy(sb + (((kc + 1) & 1) ? OFF_B1 : OFF_B0), (kc + 1) & 15, tid, 256);
        cp_wait1();
        __syncthreads();
        gemm_chunk(sb + ((kc & 1) ? OFF_B1 : OFF_B0), kc, 0, acc0);
        mlp_row(32 + 2 * kc);
        mlp_row(33 + 2 * kc);
        __syncthreads();
    }

    // ---------------- Loop 2: GEMM(h1) + interleaved epilogue(h0)
    #pragma unroll 1
    for (int kc = 0; kc < N_KC; kc++) {
        if (kc < N_KC - 1) {
            fill_b_copy(sb + (((kc + 1) & 1) ? OFF_B1 : OFF_B0), kc + 1, tid, 256);
            cp_wait1();
        } else {
            cp_wait0();
        }
        __syncthreads();
        gemm_chunk(sb + ((kc & 1) ? OFF_B1 : OFF_B0), kc, 1, acc1);
        if (kc < 8) store_frag(acc0[kc >> 2][kc & 3], 0, kc >> 2, kc & 3);
        if (kc < N_KC - 1) __syncthreads();
    }

    // ---------------- Final epilogue: half 1
    #pragma unroll
    for (int i = 0; i < 2; i++)
        #pragma unroll
        for (int j = 0; j < 4; j++)
            store_frag(acc1[i][j], 1, i, j);
}

extern "C" void kernel_launch(void* const* d_in, const int* in_sizes, int n_in,
                              void* d_out, int out_size) {
    const int*   y  = (const int*)d_in[0];
    const float* w1 = (const float*)d_in[1];
    const float* b1 = (const float*)d_in[2];
    const float* w2 = (const float*)d_in[3];
    const float* b2 = (const float*)d_in[4];
    float* out = (float*)d_out;
    const int Btot = in_sizes[0] / S;          // 65536 rows
    const int grid = Btot / TILE_M;            // 1024 CTAs

    prep_kernel<<<(N_KC * 256 * (B_STRIDE / 2) + 255) / 256, 256>>>(w2);

    cudaFuncSetAttribute(tte_kernel, cudaFuncAttributeMaxDynamicSharedMemorySize,
                         SMEM_BYTES);
    tte_kernel<<<grid, 256, SMEM_BYTES>>>(y, w1, b1, b2, out);
}

// round 7
// speedup vs baseline: 1.6587x; 1.6587x over previous
#include <cuda_runtime.h>
#include <cuda_bf16.h>
#include <cstdint>

// ---------------------------------------------------------------------------
// TargetTokenEncoder: hist/stats -> MLP(14->256, exact GELU) -> GEMM(256x256)
// Stage C via warp-level HMMA (mma.sync m16n8k16 bf16, fp32 accum),
// bf16x3 split precision: Ah*Bh + Ah*Bl + Al*Bh (rel err ~5e-6).
// R7: B pre-arranged in MMA-fragment order in global scratch; warps __ldg
//     fragments directly (no B smem, no GEMM barriers). Warp tile 64Mx32N.
//     smem = A(split) + stats = 71.7KB -> 2 CTAs/SM, big L1 carveout.
// ---------------------------------------------------------------------------

static constexpr int S      = 128;
static constexpr int TD     = 256;
static constexpr int TILE_M = 64;

static constexpr int A_STRIDE = 528;              // 256 bf16 + 8 pad (ldmatrix clean)
static constexpr int OFF_A_HI  = 0;               // 64 x 528 = 33792
static constexpr int OFF_A_LO  = 33792;
static constexpr int OFF_STATS = 67584;           // 64 x 16 f32
static constexpr int SMEM_BYTES = 71680;
static constexpr int D_A_LO = 33792;

// B fragment scratch: [ks 0..15][cgpair 0..15][lane 0..31][8 bf16]
// 8 bf16 = frag regs for cg=2*cgp (b0,b1) then cg=2*cgp+1 (b0,b1).
// Element (e): cg = 2*cgp + (e>>2), k = ks*16 + 2*(L%4) + ((e&2)?8:0) + (e&1),
//              n = cg*8 + L/4, value = w2[k][n].
__device__ __align__(16) __nv_bfloat16 g_b_hi[16 * 16 * 32 * 8];   // 128KB
__device__ __align__(16) __nv_bfloat16 g_b_lo[16 * 16 * 32 * 8];   // 128KB

__device__ __forceinline__ uint32_t smem_u32(const void* p) {
    uint32_t a;
    asm("{ .reg .u64 t; cvta.to.shared.u64 t, %1; cvt.u32.u64 %0, t; }" : "=r"(a) : "l"(p));
    return a;
}

__device__ __forceinline__ void ldm4(uint32_t* r, uint32_t addr) {
    asm volatile("ldmatrix.sync.aligned.m8n8.x4.shared.b16 {%0,%1,%2,%3}, [%4];"
                 : "=r"(r[0]), "=r"(r[1]), "=r"(r[2]), "=r"(r[3]) : "r"(addr));
}

__device__ __forceinline__ void mma_bf16(float* c, const uint32_t* a,
                                         uint32_t b0, uint32_t b1) {
    asm volatile("mma.sync.aligned.m16n8k16.row.col.f32.bf16.bf16.f32 "
                 "{%0,%1,%2,%3}, {%4,%5,%6,%7}, {%8,%9}, {%0,%1,%2,%3};"
                 : "+f"(c[0]), "+f"(c[1]), "+f"(c[2]), "+f"(c[3])
                 : "r"(a[0]), "r"(a[1]), "r"(a[2]), "r"(a[3]), "r"(b0), "r"(b1));
}

// ---------------- prep kernel: w2 -> split bf16 fragment-order scratch
__global__ __launch_bounds__(256)
void prep_kernel(const float* __restrict__ w2) {
    int idx = blockIdx.x * 256 + threadIdx.x;          // (ks<<9)|(cgp<<5)|L
    if (idx >= 8192) return;
    const int L   = idx & 31;
    const int cgp = (idx >> 5) & 15;
    const int ks  = idx >> 9;
    const int k0  = ks * 16 + 2 * (L & 3);
    const int nb  = L >> 2;
    __nv_bfloat16* oh = g_b_hi + (size_t)idx * 8;
    __nv_bfloat16* ol = g_b_lo + (size_t)idx * 8;
    #pragma unroll
    for (int e = 0; e < 8; e++) {
        const int cg = cgp * 2 + (e >> 2);
        const int kk = k0 + ((e & 2) ? 8 : 0) + (e & 1);
        const int n  = cg * 8 + nb;
        float v = __ldg(w2 + (size_t)kk * TD + n);
        __nv_bfloat16 hi = __float2bfloat16(v);
        float lo = v - __bfloat162float(hi);
        oh[e] = hi;
        ol[e] = __float2bfloat16(lo);
    }
}

__global__ __launch_bounds__(256, 2)
void tte_kernel(const int* __restrict__ y, const float* __restrict__ w1,
                const float* __restrict__ b1,
                const float* __restrict__ b2, float* __restrict__ out)
{
    extern __shared__ char smem[];
    const uint32_t sb = smem_u32(smem);
    const int tid = threadIdx.x;
    const int wid = tid >> 5;
    const int lid = tid & 31;

    float* stats = reinterpret_cast<float*>(smem + OFF_STATS);

    // ---------------- Phase 1: cooperative histogram, 4 threads per row
    {
        const int row = tid >> 2;             // 0..63
        const int sub = tid & 3;
        const int4* p = reinterpret_cast<const int4*>(
            y + ((size_t)blockIdx.x * TILE_M + row) * S) + sub * 8;
        uint32_t a0 = 0, a1 = 0, a2 = 0;      // 4x8-bit packed counters
        #pragma unroll
        for (int i = 0; i < 8; i++) {
            int4 v = __ldg(p + i);
            { int x = v.x; uint32_t b = 1u << ((x & 3) << 3);
              if (x < 4) a0 += b; else if (x < 8) a1 += b; else a2 += b; }
            { int x = v.y; uint32_t b = 1u << ((x & 3) << 3);
              if (x < 4) a0 += b; else if (x < 8) a1 += b; else a2 += b; }
            { int x = v.z; uint32_t b = 1u << ((x & 3) << 3);
              if (x < 4) a0 += b; else if (x < 8) a1 += b; else a2 += b; }
            { int x = v.w; uint32_t b = 1u << ((x & 3) << 3);
              if (x < 4) a0 += b; else if (x < 8) a1 += b; else a2 += b; }
        }
        // merge the 4 partials (counts <= 128 fit the 8-bit fields)
        a0 += __shfl_xor_sync(0xFFFFFFFFu, a0, 1);
        a1 += __shfl_xor_sync(0xFFFFFFFFu, a1, 1);
        a2 += __shfl_xor_sync(0xFFFFFFFFu, a2, 1);
        a0 += __shfl_xor_sync(0xFFFFFFFFu, a0, 2);
        a1 += __shfl_xor_sync(0xFFFFFFFFu, a1, 2);
        a2 += __shfl_xor_sync(0xFFFFFFFFu, a2, 2);
        if (sub == 0) {
            int cnt[10];
            float pr[10];
            #pragma unroll
            for (int c = 0; c < 10; c++) {
                uint32_t a = (c < 4) ? a0 : ((c < 8) ? a1 : a2);
                cnt[c] = (int)((a >> ((c & 3) * 8)) & 0xFF);
                pr[c]  = (float)cnt[c] * (1.0f / 128.0f);   // exact in fp32
            }
            float ent = 0.0f, pm = 0.0f, nnz = 0.0f;
            #pragma unroll
            for (int c = 0; c < 10; c++) {
                ent -= pr[c] * logf(pr[c] + 1e-6f);         // p==0 -> exactly 0
                pm   = fmaxf(pm, pr[c]);
                nnz += (cnt[c] > 0) ? 1.0f : 0.0f;
            }
            float* sr = stats + row * 16;
            #pragma unroll
            for (int c = 0; c < 10; c++) sr[c] = pr[c];
            sr[10] = nnz; sr[11] = ent; sr[12] = 128.0f; sr[13] = pm;
            sr[14] = 0.0f; sr[15] = 0.0f;
        }
    }
    __syncthreads();

    // ---------------- Phase 2: stage-B MLP. thread t owns h column n=t.
    {
        float wv[14];
        #pragma unroll
        for (int k = 0; k < 14; k++) wv[k] = __ldg(w1 + k * TD + tid);
        const float bb = __ldg(b1 + tid);
        for (int r = 0; r < TILE_M; r++) {
            const float4* sp = reinterpret_cast<const float4*>(stats + r * 16);
            float4 s0 = sp[0], s1 = sp[1], s2 = sp[2], s3 = sp[3];
            float x = bb;
            x = fmaf(s0.x, wv[0], x);  x = fmaf(s0.y, wv[1], x);
            x = fmaf(s0.z, wv[2], x);  x = fmaf(s0.w, wv[3], x);
            x = fmaf(s1.x, wv[4], x);  x = fmaf(s1.y, wv[5], x);
            x = fmaf(s1.z, wv[6], x);  x = fmaf(s1.w, wv[7], x);
            x = fmaf(s2.x, wv[8], x);  x = fmaf(s2.y, wv[9], x);
            x = fmaf(s2.z, wv[10], x); x = fmaf(s2.w, wv[11], x);
            x = fmaf(s3.x, wv[12], x); x = fmaf(s3.y, wv[13], x);
            float g = 0.5f * x * (1.0f + erff(x * 0.707106781186547524f));
            __nv_bfloat16 hi = __float2bfloat16(g);
            float rem = g - __bfloat162float(hi);
            __nv_bfloat16 lo = __float2bfloat16(rem);
            const uint32_t off = (uint32_t)(r * A_STRIDE + tid * 2);
            *reinterpret_cast<__nv_bfloat16*>(smem + OFF_A_HI + off) = hi;
            *reinterpret_cast<__nv_bfloat16*>(smem + OFF_A_LO + off) = lo;
        }
    }
    __syncthreads();   // last barrier — GEMM runs barrier-free

    // ---------------- Phase 3: GEMM h[64,256] @ w2 slice, bf16x3 HMMA.
    // Warp tile 64M x 32N: warp wid owns cols [wid*32, wid*32+32).
    const int wn = wid;                // 0..7
    const int j8 = lid >> 3;
    const int lr = lid & 7;

    uint32_t aoff[4];                  // 4 m-tiles of 16 rows
    #pragma unroll
    for (int i = 0; i < 4; i++)
        aoff[i] = sb + OFF_A_HI
                + (uint32_t)((i * 16 + ((j8 & 1) << 3) + lr) * A_STRIDE)
                + (uint32_t)((j8 >> 1) << 4);

    const uint4* gbh = reinterpret_cast<const uint4*>(g_b_hi);
    const uint4* gbl = reinterpret_cast<const uint4*>(g_b_lo);

    float acc[4][4][4];                // [mtile][cg][frag]
    #pragma unroll
    for (int i = 0; i < 4; i++)
        #pragma unroll
        for (int j = 0; j < 4; j++)
            #pragma unroll
            for (int q = 0; q < 4; q++) acc[i][j][q] = 0.0f;

    #pragma unroll
    for (int ks = 0; ks < 16; ks++) {
        // B fragments (warp-private, straight from L1/L2)
        uint4 fH[2], fL[2];
        #pragma unroll
        for (int c = 0; c < 2; c++) {
            const int fidx = ((ks * 16 + wn * 2 + c) << 5) + lid;
            fH[c] = __ldg(gbh + fidx);
            fL[c] = __ldg(gbl + fidx);
        }
        const uint32_t ka = (uint32_t)(ks * 32);
        // m-tiles 0,1
        #pragma unroll
        for (int half = 0; half < 2; half++) {
            uint32_t aH[2][4], aL[2][4];
            #pragma unroll
            for (int u = 0; u < 2; u++) {
                ldm4(aH[u], aoff[half * 2 + u] + ka);
                ldm4(aL[u], aoff[half * 2 + u] + ka + D_A_LO);
            }
            #pragma unroll
            for (int u = 0; u < 2; u++) {
                const int i = half * 2 + u;
                #pragma unroll
                for (int cg = 0; cg < 4; cg++) {
                    const uint4& bh = fH[cg >> 1];
                    const uint4& bl = fL[cg >> 1];
                    const uint32_t bh0 = (cg & 1) ? bh.z : bh.x;
                    const uint32_t bh1 = (cg & 1) ? bh.w : bh.y;
                    const uint32_t bl0 = (cg & 1) ? bl.z : bl.x;
                    const uint32_t bl1 = (cg & 1) ? bl.w : bl.y;
                    mma_bf16(acc[i][cg], aH[u], bh0, bh1);   // Ah*Bh
                    mma_bf16(acc[i][cg], aH[u], bl0, bl1);   // Ah*Bl
                    mma_bf16(acc[i][cg], aL[u], bh0, bh1);   // Al*Bh
                }
            }
        }
    }

    // ---------------- Epilogue (b2 from gmem; L1/L2 resident)
    {
        const int g  = lid >> 2;
        const int tg = lid & 3;
        const size_t rbase = (size_t)blockIdx.x * TILE_M;
        #pragma unroll
        for (int i = 0; i < 4; i++) {
            #pragma unroll
            for (int cg = 0; cg < 4; cg++) {
                const int col = wn * 32 + cg * 8 + tg * 2;
                const float2 bbv = __ldg(reinterpret_cast<const float2*>(b2 + col));
                const size_t r0 = rbase + i * 16 + g;
                *reinterpret_cast<float2*>(out + r0 * TD + col) =
                    make_float2(acc[i][cg][0] + bbv.x, acc[i][cg][1] + bbv.y);
                *reinterpret_cast<float2*>(out + (r0 + 8) * TD + col) =
                    make_float2(acc[i][cg][2] + bbv.x, acc[i][cg][3] + bbv.y);
            }
        }
    }
}

extern "C" void kernel_launch(void* const* d_in, const int* in_sizes, int n_in,
                              void* d_out, int out_size) {
    const int*   y  = (const int*)d_in[0];
    const float* w1 = (const float*)d_in[1];
    const float* b1 = (const float*)d_in[2];
    const float* w2 = (const float*)d_in[3];
    const float* b2 = (const float*)d_in[4];
    float* out = (float*)d_out;
    const int Btot = in_sizes[0] / S;          // 65536 rows
    const int grid = Btot / TILE_M;            // 1024 CTAs

    prep_kernel<<<32, 256>>>(w2);              // 8192 fragment groups

    cudaFuncSetAttribute(tte_kernel, cudaFuncAttributeMaxDynamicSharedMemorySize,
                         SMEM_BYTES);
    tte_kernel<<<grid, 256, SMEM_BYTES>>>(y, w1, b1, b2, out);
}

// round 8
// speedup vs baseline: 1.9740x; 1.1901x over previous
#include <cuda_runtime.h>
#include <cuda_fp16.h>
#include <cstdint>

// ---------------------------------------------------------------------------
// TargetTokenEncoder: hist/stats -> MLP(14->256, exact GELU) -> GEMM(256x256)
// Stage C via warp-level HMMA (mma.sync m16n8k16 f16, fp32 accum),
// fp16x2 split: A single fp16 plane, B split fp16 hi+lo.
//   C = A*Bh + A*Bl ; residual = deltaA*B ~ 1.4e-4 rel (fp16 rounding of h).
// R8: 2 MMA passes (was 3), single A plane (ldsm traffic halved),
//     B-fragment register prefetch pipeline (no smem B, no GEMM barriers).
// ---------------------------------------------------------------------------

static constexpr int S      = 128;
static constexpr int TD     = 256;
static constexpr int TILE_M = 64;

static constexpr int A_STRIDE = 528;   // 256 fp16 + 8 pad (odd 16B multiple)
static constexpr int OFF_A     = 0;    // 64 x 528 = 33792
static constexpr int OFF_STATS = 33792;
static constexpr int SMEM_BYTES = 37888;

// B fragment scratch: [ks 0..15][cgpair 0..15][lane 0..31][8 fp16]
// Element (e): cg = 2*cgp + (e>>2), k = ks*16 + 2*(L%4) + ((e&2)?8:0) + (e&1),
//              n = cg*8 + L/4, value = w2[k][n]. (layout verified in R7)
__device__ __align__(16) __half g_b_hi[16 * 16 * 32 * 8];   // 128KB
__device__ __align__(16) __half g_b_lo[16 * 16 * 32 * 8];   // 128KB

__device__ __forceinline__ uint32_t smem_u32(const void* p) {
    uint32_t a;
    asm("{ .reg .u64 t; cvta.to.shared.u64 t, %1; cvt.u32.u64 %0, t; }" : "=r"(a) : "l"(p));
    return a;
}

__device__ __forceinline__ void ldm4(uint32_t* r, uint32_t addr) {
    asm volatile("ldmatrix.sync.aligned.m8n8.x4.shared.b16 {%0,%1,%2,%3}, [%4];"
                 : "=r"(r[0]), "=r"(r[1]), "=r"(r[2]), "=r"(r[3]) : "r"(addr));
}

__device__ __forceinline__ void mma_f16(float* c, const uint32_t* a,
                                        uint32_t b0, uint32_t b1) {
    asm volatile("mma.sync.aligned.m16n8k16.row.col.f32.f16.f16.f32 "
                 "{%0,%1,%2,%3}, {%4,%5,%6,%7}, {%8,%9}, {%0,%1,%2,%3};"
                 : "+f"(c[0]), "+f"(c[1]), "+f"(c[2]), "+f"(c[3])
                 : "r"(a[0]), "r"(a[1]), "r"(a[2]), "r"(a[3]), "r"(b0), "r"(b1));
}

// ---------------- prep kernel: w2 -> split fp16 fragment-order scratch
__global__ __launch_bounds__(256)
void prep_kernel(const float* __restrict__ w2) {
    int idx = blockIdx.x * 256 + threadIdx.x;          // (ks<<9)|(cgp<<5)|L
    if (idx >= 8192) return;
    const int L   = idx & 31;
    const int cgp = (idx >> 5) & 15;
    const int ks  = idx >> 9;
    const int k0  = ks * 16 + 2 * (L & 3);
    const int nb  = L >> 2;
    __half* oh = g_b_hi + (size_t)idx * 8;
    __half* ol = g_b_lo + (size_t)idx * 8;
    #pragma unroll
    for (int e = 0; e < 8; e++) {
        const int cg = cgp * 2 + (e >> 2);
        const int kk = k0 + ((e & 2) ? 8 : 0) + (e & 1);
        const int n  = cg * 8 + nb;
        float v = __ldg(w2 + (size_t)kk * TD + n);
        __half hi = __float2half_rn(v);
        float lo = v - __half2float(hi);
        oh[e] = hi;
        ol[e] = __float2half_rn(lo);
    }
}

__global__ __launch_bounds__(256, 2)
void tte_kernel(const int* __restrict__ y, const float* __restrict__ w1,
                const float* __restrict__ b1,
                const float* __restrict__ b2, float* __restrict__ out)
{
    extern __shared__ char smem[];
    const uint32_t sb = smem_u32(smem);
    const int tid = threadIdx.x;
    const int wid = tid >> 5;
    const int lid = tid & 31;

    float* stats = reinterpret_cast<float*>(smem + OFF_STATS);

    // ---------------- Phase 1: cooperative histogram, 4 threads per row
    {
        const int row = tid >> 2;             // 0..63
        const int sub = tid & 3;
        const int4* p = reinterpret_cast<const int4*>(
            y + ((size_t)blockIdx.x * TILE_M + row) * S) + sub * 8;
        uint32_t a0 = 0, a1 = 0, a2 = 0;      // 4x8-bit packed counters
        #pragma unroll
        for (int i = 0; i < 8; i++) {
            int4 v = __ldg(p + i);
            { int x = v.x; uint32_t b = 1u << ((x & 3) << 3);
              if (x < 4) a0 += b; else if (x < 8) a1 += b; else a2 += b; }
            { int x = v.y; uint32_t b = 1u << ((x & 3) << 3);
              if (x < 4) a0 += b; else if (x < 8) a1 += b; else a2 += b; }
            { int x = v.z; uint32_t b = 1u << ((x & 3) << 3);
              if (x < 4) a0 += b; else if (x < 8) a1 += b; else a2 += b; }
            { int x = v.w; uint32_t b = 1u << ((x & 3) << 3);
              if (x < 4) a0 += b; else if (x < 8) a1 += b; else a2 += b; }
        }
        a0 += __shfl_xor_sync(0xFFFFFFFFu, a0, 1);
        a1 += __shfl_xor_sync(0xFFFFFFFFu, a1, 1);
        a2 += __shfl_xor_sync(0xFFFFFFFFu, a2, 1);
        a0 += __shfl_xor_sync(0xFFFFFFFFu, a0, 2);
        a1 += __shfl_xor_sync(0xFFFFFFFFu, a1, 2);
        a2 += __shfl_xor_sync(0xFFFFFFFFu, a2, 2);
        if (sub == 0) {
            int cnt[10];
            float pr[10];
            #pragma unroll
            for (int c = 0; c < 10; c++) {
                uint32_t a = (c < 4) ? a0 : ((c < 8) ? a1 : a2);
                cnt[c] = (int)((a >> ((c & 3) * 8)) & 0xFF);
                pr[c]  = (float)cnt[c] * (1.0f / 128.0f);   // exact in fp32
            }
            float ent = 0.0f, pm = 0.0f, nnz = 0.0f;
            #pragma unroll
            for (int c = 0; c < 10; c++) {
                ent -= pr[c] * logf(pr[c] + 1e-6f);         // p==0 -> exactly 0
                pm   = fmaxf(pm, pr[c]);
                nnz += (cnt[c] > 0) ? 1.0f : 0.0f;
            }
            float* sr = stats + row * 16;
            #pragma unroll
            for (int c = 0; c < 10; c++) sr[c] = pr[c];
            sr[10] = nnz; sr[11] = ent; sr[12] = 128.0f; sr[13] = pm;
            sr[14] = 0.0f; sr[15] = 0.0f;
        }
    }
    __syncthreads();

    // ---------------- Phase 2: stage-B MLP. thread t owns h column n=t.
    {
        float wv[14];
        #pragma unroll
        for (int k = 0; k < 14; k++) wv[k] = __ldg(w1 + k * TD + tid);
        const float bb = __ldg(b1 + tid);
        #pragma unroll 4
        for (int r = 0; r < TILE_M; r++) {
            const float4* sp = reinterpret_cast<const float4*>(stats + r * 16);
            float4 s0 = sp[0], s1 = sp[1], s2 = sp[2], s3 = sp[3];
            float x = bb;
            x = fmaf(s0.x, wv[0], x);  x = fmaf(s0.y, wv[1], x);
            x = fmaf(s0.z, wv[2], x);  x = fmaf(s0.w, wv[3], x);
            x = fmaf(s1.x, wv[4], x);  x = fmaf(s1.y, wv[5], x);
            x = fmaf(s1.z, wv[6], x);  x = fmaf(s1.w, wv[7], x);
            x = fmaf(s2.x, wv[8], x);  x = fmaf(s2.y, wv[9], x);
            x = fmaf(s2.z, wv[10], x); x = fmaf(s2.w, wv[11], x);
            x = fmaf(s3.x, wv[12], x); x = fmaf(s3.y, wv[13], x);
            float g = 0.5f * x * (1.0f + erff(x * 0.707106781186547524f));
            *reinterpret_cast<__half*>(smem + OFF_A
                + (uint32_t)(r * A_STRIDE + tid * 2)) = __float2half_rn(g);
        }
    }
    __syncthreads();   // last barrier — GEMM runs barrier-free

    // ---------------- Phase 3: GEMM h[64,256] @ w2 slice, fp16x2 HMMA.
    // Warp tile 64M x 32N: warp wid owns cols [wid*32, wid*32+32).
    const int wn = wid;                // 0..7
    const int j8 = lid >> 3;
    const int lr = lid & 7;

    uint32_t aoff[4];                  // 4 m-tiles of 16 rows
    #pragma unroll
    for (int i = 0; i < 4; i++)
        aoff[i] = sb + OFF_A
                + (uint32_t)((i * 16 + ((j8 & 1) << 3) + lr) * A_STRIDE)
                + (uint32_t)((j8 >> 1) << 4);

    const uint4* gbh = reinterpret_cast<const uint4*>(g_b_hi);
    const uint4* gbl = reinterpret_cast<const uint4*>(g_b_lo);

    float acc[4][4][4];                // [mtile][cg][frag]
    #pragma unroll
    for (int i = 0; i < 4; i++)
        #pragma unroll
        for (int j = 0; j < 4; j++)
            #pragma unroll
            for (int q = 0; q < 4; q++) acc[i][j][q] = 0.0f;

    // prefetch pipeline: B fragments for ks=0
    uint4 fH[2], fL[2];
    #pragma unroll
    for (int c = 0; c < 2; c++) {
        const int fidx = ((wn * 2 + c) << 5) + lid;
        fH[c] = __ldg(gbh + fidx);
        fL[c] = __ldg(gbl + fidx);
    }

    #pragma unroll
    for (int ks = 0; ks < 16; ks++) {
        // prefetch ks+1 while ks computes
        uint4 nH[2], nL[2];
        if (ks < 15) {
            #pragma unroll
            for (int c = 0; c < 2; c++) {
                const int fidx = (((ks + 1) * 16 + wn * 2 + c) << 5) + lid;
                nH[c] = __ldg(gbh + fidx);
                nL[c] = __ldg(gbl + fidx);
            }
        }
        const uint32_t ka = (uint32_t)(ks * 32);
        uint32_t af[4][4];
        #pragma unroll
        for (int i = 0; i < 4; i++) ldm4(af[i], aoff[i] + ka);
        #pragma unroll
        for (int i = 0; i < 4; i++) {
            #pragma unroll
            for (int cg = 0; cg < 4; cg++) {
                const uint4& bh = fH[cg >> 1];
                const uint4& bl = fL[cg >> 1];
                const uint32_t bh0 = (cg & 1) ? bh.z : bh.x;
                const uint32_t bh1 = (cg & 1) ? bh.w : bh.y;
                const uint32_t bl0 = (cg & 1) ? bl.z : bl.x;
                const uint32_t bl1 = (cg & 1) ? bl.w : bl.y;
                mma_f16(acc[i][cg], af[i], bh0, bh1);   // A*Bh
                mma_f16(acc[i][cg], af[i], bl0, bl1);   // A*Bl
            }
        }
        #pragma unroll
        for (int c = 0; c < 2; c++) { fH[c] = nH[c]; fL[c] = nL[c]; }
    }

    // ---------------- Epilogue (b2 from gmem; L1/L2 resident)
    {
        const int g  = lid >> 2;
        const int tg = lid & 3;
        const size_t rbase = (size_t)blockIdx.x * TILE_M;
        #pragma unroll
        for (int i = 0; i < 4; i++) {
            #pragma unroll
            for (int cg = 0; cg < 4; cg++) {
                const int col = wn * 32 + cg * 8 + tg * 2;
                const float2 bbv = __ldg(reinterpret_cast<const float2*>(b2 + col));
                const size_t r0 = rbase + i * 16 + g;
                *reinterpret_cast<float2*>(out + r0 * TD + col) =
                    make_float2(acc[i][cg][0] + bbv.x, acc[i][cg][1] + bbv.y);
                *reinterpret_cast<float2*>(out + (r0 + 8) * TD + col) =
                    make_float2(acc[i][cg][2] + bbv.x, acc[i][cg][3] + bbv.y);
            }
        }
    }
}

extern "C" void kernel_launch(void* const* d_in, const int* in_sizes, int n_in,
                              void* d_out, int out_size) {
    const int*   y  = (const int*)d_in[0];
    const float* w1 = (const float*)d_in[1];
    const float* b1 = (const float*)d_in[2];
    const float* w2 = (const float*)d_in[3];
    const float* b2 = (const float*)d_in[4];
    float* out = (float*)d_out;
    const int Btot = in_sizes[0] / S;          // 65536 rows
    const int grid = Btot / TILE_M;            // 1024 CTAs

    prep_kernel<<<32, 256>>>(w2);              // 8192 fragment groups

    cudaFuncSetAttribute(tte_kernel, cudaFuncAttributeMaxDynamicSharedMemorySize,
                         SMEM_BYTES);
    tte_kernel<<<grid, 256, SMEM_BYTES>>>(y, w1, b1, b2, out);
}

// round 9
// speedup vs baseline: 2.1162x; 1.0721x over previous
#include <cuda_runtime.h>
#include <cuda_fp16.h>
#include <cstdint>

// ---------------------------------------------------------------------------
// TargetTokenEncoder: hist/stats -> MLP(14->256, exact GELU) -> GEMM(256x256)
// Stage C via warp-level HMMA (mma.sync m16n8k16 f16, fp32 accum),
// fp16x2 split: A single fp16 plane, B split fp16 hi+lo (rel err ~2e-4).
// R9: TILE_M=32, acc 32 regs, __launch_bounds__(256,3) -> 3 CTAs/SM (24
//     warps) to cover latency. B frag-direct LDG, barrier-free GEMM.
// ---------------------------------------------------------------------------

static constexpr int S      = 128;
static constexpr int TD     = 256;
static constexpr int TILE_M = 32;

static constexpr int A_STRIDE = 528;   // 256 fp16 + 8 pad (odd 16B multiple)
static constexpr int OFF_A     = 0;    // 32 x 528 = 16896
static constexpr int OFF_STATS = 16896;  // 32 x 16 f32 = 2048
static constexpr int SMEM_BYTES = 19456;

// B fragment scratch: [ks 0..15][cgpair 0..15][lane 0..31][8 fp16]
// Element (e): cg = 2*cgp + (e>>2), k = ks*16 + 2*(L%4) + ((e&2)?8:0) + (e&1),
//              n = cg*8 + L/4, value = w2[k][n]. (layout verified R7/R8)
__device__ __align__(16) __half g_b_hi[16 * 16 * 32 * 8];   // 128KB
__device__ __align__(16) __half g_b_lo[16 * 16 * 32 * 8];   // 128KB

__device__ __forceinline__ uint32_t smem_u32(const void* p) {
    uint32_t a;
    asm("{ .reg .u64 t; cvta.to.shared.u64 t, %1; cvt.u32.u64 %0, t; }" : "=r"(a) : "l"(p));
    return a;
}

__device__ __forceinline__ void ldm4(uint32_t* r, uint32_t addr) {
    asm volatile("ldmatrix.sync.aligned.m8n8.x4.shared.b16 {%0,%1,%2,%3}, [%4];"
                 : "=r"(r[0]), "=r"(r[1]), "=r"(r[2]), "=r"(r[3]) : "r"(addr));
}

__device__ __forceinline__ void mma_f16(float* c, const uint32_t* a,
                                        uint32_t b0, uint32_t b1) {
    asm volatile("mma.sync.aligned.m16n8k16.row.col.f32.f16.f16.f32 "
                 "{%0,%1,%2,%3}, {%4,%5,%6,%7}, {%8,%9}, {%0,%1,%2,%3};"
                 : "+f"(c[0]), "+f"(c[1]), "+f"(c[2]), "+f"(c[3])
                 : "r"(a[0]), "r"(a[1]), "r"(a[2]), "r"(a[3]), "r"(b0), "r"(b1));
}

// ---------------- prep kernel: w2 -> split fp16 fragment-order scratch
__global__ __launch_bounds__(256)
void prep_kernel(const float* __restrict__ w2) {
    int idx = blockIdx.x * 256 + threadIdx.x;          // (ks<<9)|(cgp<<5)|L
    if (idx >= 8192) return;
    const int L   = idx & 31;
    const int cgp = (idx >> 5) & 15;
    const int ks  = idx >> 9;
    const int k0  = ks * 16 + 2 * (L & 3);
    const int nb  = L >> 2;
    __half* oh = g_b_hi + (size_t)idx * 8;
    __half* ol = g_b_lo + (size_t)idx * 8;
    #pragma unroll
    for (int e = 0; e < 8; e++) {
        const int cg = cgp * 2 + (e >> 2);
        const int kk = k0 + ((e & 2) ? 8 : 0) + (e & 1);
        const int n  = cg * 8 + nb;
        float v = __ldg(w2 + (size_t)kk * TD + n);
        __half hi = __float2half_rn(v);
        float lo = v - __half2float(hi);
        oh[e] = hi;
        ol[e] = __float2half_rn(lo);
    }
}

__global__ __launch_bounds__(256, 3)
void tte_kernel(const int* __restrict__ y, const float* __restrict__ w1,
                const float* __restrict__ b1,
                const float* __restrict__ b2, float* __restrict__ out)
{
    extern __shared__ char smem[];
    const uint32_t sb = smem_u32(smem);
    const int tid = threadIdx.x;
    const int wid = tid >> 5;
    const int lid = tid & 31;

    float* stats = reinterpret_cast<float*>(smem + OFF_STATS);

    // ---------------- Phase 1: cooperative histogram, 8 threads per row
    {
        const int row = tid >> 3;             // 0..31
        const int sub = tid & 7;
        const int4* p = reinterpret_cast<const int4*>(
            y + ((size_t)blockIdx.x * TILE_M + row) * S) + sub * 4;
        uint32_t a0 = 0, a1 = 0, a2 = 0;      // 4x8-bit packed counters
        #pragma unroll
        for (int i = 0; i < 4; i++) {
            int4 v = __ldg(p + i);
            { int x = v.x; uint32_t b = 1u << ((x & 3) << 3);
              if (x < 4) a0 += b; else if (x < 8) a1 += b; else a2 += b; }
            { int x = v.y; uint32_t b = 1u << ((x & 3) << 3);
              if (x < 4) a0 += b; else if (x < 8) a1 += b; else a2 += b; }
            { int x = v.z; uint32_t b = 1u << ((x & 3) << 3);
              if (x < 4) a0 += b; else if (x < 8) a1 += b; else a2 += b; }
            { int x = v.w; uint32_t b = 1u << ((x & 3) << 3);
              if (x < 4) a0 += b; else if (x < 8) a1 += b; else a2 += b; }
        }
        #pragma unroll
        for (int d = 1; d < 8; d <<= 1) {
            a0 += __shfl_xor_sync(0xFFFFFFFFu, a0, d);
            a1 += __shfl_xor_sync(0xFFFFFFFFu, a1, d);
            a2 += __shfl_xor_sync(0xFFFFFFFFu, a2, d);
        }
        if (sub == 0) {
            int cnt[10];
            float pr[10];
            #pragma unroll
            for (int c = 0; c < 10; c++) {
                uint32_t a = (c < 4) ? a0 : ((c < 8) ? a1 : a2);
                cnt[c] = (int)((a >> ((c & 3) * 8)) & 0xFF);
                pr[c]  = (float)cnt[c] * (1.0f / 128.0f);   // exact in fp32
            }
            float ent = 0.0f, pm = 0.0f, nnz = 0.0f;
            #pragma unroll
            for (int c = 0; c < 10; c++) {
                ent -= pr[c] * logf(pr[c] + 1e-6f);         // p==0 -> exactly 0
                pm   = fmaxf(pm, pr[c]);
                nnz += (cnt[c] > 0) ? 1.0f : 0.0f;
            }
            float* sr = stats + row * 16;
            #pragma unroll
            for (int c = 0; c < 10; c++) sr[c] = pr[c];
            sr[10] = nnz; sr[11] = ent; sr[12] = 128.0f; sr[13] = pm;
            sr[14] = 0.0f; sr[15] = 0.0f;
        }
    }
    __syncthreads();

    // ---------------- Phase 2: stage-B MLP. thread t owns h column n=t.
    {
        float wv[14];
        #pragma unroll
        for (int k = 0; k < 14; k++) wv[k] = __ldg(w1 + k * TD + tid);
        const float bb = __ldg(b1 + tid);
        #pragma unroll 4
        for (int r = 0; r < TILE_M; r++) {
            const float4* sp = reinterpret_cast<const float4*>(stats + r * 16);
            float4 s0 = sp[0], s1 = sp[1], s2 = sp[2], s3 = sp[3];
            float x = bb;
            x = fmaf(s0.x, wv[0], x);  x = fmaf(s0.y, wv[1], x);
            x = fmaf(s0.z, wv[2], x);  x = fmaf(s0.w, wv[3], x);
            x = fmaf(s1.x, wv[4], x);  x = fmaf(s1.y, wv[5], x);
            x = fmaf(s1.z, wv[6], x);  x = fmaf(s1.w, wv[7], x);
            x = fmaf(s2.x, wv[8], x);  x = fmaf(s2.y, wv[9], x);
            x = fmaf(s2.z, wv[10], x); x = fmaf(s2.w, wv[11], x);
            x = fmaf(s3.x, wv[12], x); x = fmaf(s3.y, wv[13], x);
            float g = 0.5f * x * (1.0f + erff(x * 0.707106781186547524f));
            *reinterpret_cast<__half*>(smem + OFF_A
                + (uint32_t)(r * A_STRIDE + tid * 2)) = __float2half_rn(g);
        }
    }
    __syncthreads();   // last barrier — GEMM runs barrier-free

    // ---------------- Phase 3: GEMM h[32,256] @ w2 slice, fp16x2 HMMA.
    // Warp tile 32M x 32N: warp wid owns cols [wid*32, wid*32+32).
    const int wn = wid;                // 0..7
    const int j8 = lid >> 3;
    const int lr = lid & 7;

    uint32_t aoff[2];                  // 2 m-tiles of 16 rows
    #pragma unroll
    for (int i = 0; i < 2; i++)
        aoff[i] = sb + OFF_A
                + (uint32_t)((i * 16 + ((j8 & 1) << 3) + lr) * A_STRIDE)
                + (uint32_t)((j8 >> 1) << 4);

    const uint4* gbh = reinterpret_cast<const uint4*>(g_b_hi);
    const uint4* gbl = reinterpret_cast<const uint4*>(g_b_lo);

    float acc[2][4][4];                // [mtile][cg][frag] = 32 regs
    #pragma unroll
    for (int i = 0; i < 2; i++)
        #pragma unroll
        for (int j = 0; j < 4; j++)
            #pragma unroll
            for (int q = 0; q < 4; q++) acc[i][j][q] = 0.0f;

    // prefetch pipeline: B fragments for ks=0
    uint4 fH[2], fL[2];
    #pragma unroll
    for (int c = 0; c < 2; c++) {
        const int fidx = ((wn * 2 + c) << 5) + lid;
        fH[c] = __ldg(gbh + fidx);
        fL[c] = __ldg(gbl + fidx);
    }

    #pragma unroll
    for (int ks = 0; ks < 16; ks++) {
        uint4 nH[2], nL[2];
        if (ks < 15) {
            #pragma unroll
            for (int c = 0; c < 2; c++) {
                const int fidx = (((ks + 1) * 16 + wn * 2 + c) << 5) + lid;
                nH[c] = __ldg(gbh + fidx);
                nL[c] = __ldg(gbl + fidx);
            }
        }
        const uint32_t ka = (uint32_t)(ks * 32);
        uint32_t af[2][4];
        #pragma unroll
        for (int i = 0; i < 2; i++) ldm4(af[i], aoff[i] + ka);
        #pragma unroll
        for (int i = 0; i < 2; i++) {
            #pragma unroll
            for (int cg = 0; cg < 4; cg++) {
                const uint4& bh = fH[cg >> 1];
                const uint4& bl = fL[cg >> 1];
                const uint32_t bh0 = (cg & 1) ? bh.z : bh.x;
                const uint32_t bh1 = (cg & 1) ? bh.w : bh.y;
                const uint32_t bl0 = (cg & 1) ? bl.z : bl.x;
                const uint32_t bl1 = (cg & 1) ? bl.w : bl.y;
                mma_f16(acc[i][cg], af[i], bh0, bh1);   // A*Bh
                mma_f16(acc[i][cg], af[i], bl0, bl1);   // A*Bl
            }
        }
        #pragma unroll
        for (int c = 0; c < 2; c++) { fH[c] = nH[c]; fL[c] = nL[c]; }
    }

    // ---------------- Epilogue (b2 from gmem; L1/L2 resident)
    {
        const int g  = lid >> 2;
        const int tg = lid & 3;
        const size_t rbase = (size_t)blockIdx.x * TILE_M;
        #pragma unroll
        for (int i = 0; i < 2; i++) {
            #pragma unroll
            for (int cg = 0; cg < 4; cg++) {
                const int col = wn * 32 + cg * 8 + tg * 2;
                const float2 bbv = __ldg(reinterpret_cast<const float2*>(b2 + col));
                const size_t r0 = rbase + i * 16 + g;
                *reinterpret_cast<float2*>(out + r0 * TD + col) =
                    make_float2(acc[i][cg][0] + bbv.x, acc[i][cg][1] + bbv.y);
                *reinterpret_cast<float2*>(out + (r0 + 8) * TD + col) =
                    make_float2(acc[i][cg][2] + bbv.x, acc[i][cg][3] + bbv.y);
            }
        }
    }
}

extern "C" void kernel_launch(void* const* d_in, const int* in_sizes, int n_in,
                              void* d_out, int out_size) {
    const int*   y  = (const int*)d_in[0];
    const float* w1 = (const float*)d_in[1];
    const float* b1 = (const float*)d_in[2];
    const float* w2 = (const float*)d_in[3];
    const float* b2 = (const float*)d_in[4];
    float* out = (float*)d_out;
    const int Btot = in_sizes[0] / S;          // 65536 rows
    const int grid = Btot / TILE_M;            // 2048 CTAs

    prep_kernel<<<32, 256>>>(w2);              // 8192 fragment groups

    cudaFuncSetAttribute(tte_kernel, cudaFuncAttributeMaxDynamicSharedMemorySize,
                         SMEM_BYTES);
    tte_kernel<<<grid, 256, SMEM_BYTES>>>(y, w1, b1, b2, out);
}